// round 11
// baseline (speedup 1.0000x reference)
#include <cuda_runtime.h>
#include <float.h>

// ROI max pool, three-phase:
//  1) batched float4 transpose: [2,256,50,50] -> g_feat_t [2,50,50,256];
//     each block moves 32hw x 128ch (4 tiles) -> MLP=4, 316 blocks
//  2) prep: per-(roi,bin) bounds -> g_meta (keeps pool at ~32 regs)
//  3) pool: block = (i, cg, n), 7 warps = 7 j-bins of ONE i-row (identical
//     trip counts -> no sync slack); warp = bin x 128 ch, width<=8 unrolled
//     (high MLP); smem-staged, direct coalesced writes to out (no scratch).

#define OUTP 7
#define NBINS 49
#define CCH  256
#define HH   50
#define WW   50
#define HWSZ (HH * WW)
#define BB   2
#define CS   (CCH / 4)

__device__ __align__(16) float g_feat_t[BB * HWSZ * CCH];   // 5.12 MB
__device__ int4 g_meta[128 * NBINS];

// ---------------- 1) transpose, 4 tiles per block ----------------
// grid (79, 2, 2): x = hw tile (32), y = 128-ch block, z = b; 256 threads.
__global__ __launch_bounds__(256) void transpose_kernel(const float* __restrict__ feat)
{
    __shared__ float tile[4][32][33];
    int b   = blockIdx.z;
    int c0  = blockIdx.y * 128;
    int hw0 = blockIdx.x * 32;
    int t   = threadIdx.x;

    int cl = t >> 3;            // 0..31
    int h4 = (t & 7) * 4;       // 0,4,...,28
    int hw = hw0 + h4;

    // 4 independent loads (different channel tiles), then one sync
    float4 v[4];
    if (hw < HWSZ) {
        #pragma unroll
        for (int ct = 0; ct < 4; ++ct)
            v[ct] = __ldg((const float4*)
                (feat + ((size_t)b * CCH + c0 + ct * 32 + cl) * HWSZ + hw));
        #pragma unroll
        for (int ct = 0; ct < 4; ++ct) {
            tile[ct][cl][h4 + 0] = v[ct].x;
            tile[ct][cl][h4 + 1] = v[ct].y;
            tile[ct][cl][h4 + 2] = v[ct].z;
            tile[ct][cl][h4 + 3] = v[ct].w;
        }
    }
    __syncthreads();

    int hwl = t >> 3;           // 0..31
    int c4  = (t & 7) * 4;      // 0,4,...,28
    int hww = hw0 + hwl;
    if (hww < HWSZ) {
        float* drow = g_feat_t + ((size_t)b * HWSZ + hww) * CCH + c0;
        #pragma unroll
        for (int ct = 0; ct < 4; ++ct) {
            float4 o;
            o.x = tile[ct][c4 + 0][hwl];
            o.y = tile[ct][c4 + 1][hwl];
            o.z = tile[ct][c4 + 2][hwl];
            o.w = tile[ct][c4 + 3][hwl];
            *(float4*)(drow + ct * 32 + c4) = o;
        }
    }
}

// ---------------- 2) prep ----------------
__global__ void prep_kernel(const float* __restrict__ rois)
{
    int t = blockIdx.x * blockDim.x + threadIdx.x;
    if (t >= 128 * NBINS) return;
    int n  = t / NBINS;
    int ij = t - n * NBINS;
    int i  = ij / OUTP;
    int j  = ij - i * OUTP;

    const float* r = rois + n * 5;
    int im = (int)rintf(r[0]);
    int x1 = (int)rintf(r[1] * 0.0625f);
    int y1 = (int)rintf(r[2] * 0.0625f);
    int x2 = (int)rintf(r[3] * 0.0625f);
    int y2 = (int)rintf(r[4] * 0.0625f);
    unsigned h = (unsigned)(y2 - y1 + 1);
    unsigned w = (unsigned)(x2 - x1 + 1);

    int ys = (int)((unsigned)(i * h) / 7u) + y1;
    int ye = (int)(((unsigned)((i + 1) * h) + 6u) / 7u) + y1;
    int xs = (int)((unsigned)(j * w) / 7u) + x1;
    int xe = (int)(((unsigned)((j + 1) * w) + 6u) / 7u) + x1;
    ye = min(ye, HH);  xe = min(xe, WW);

    int4 m;
    m.x = im * HWSZ + ys * WW + xs;
    m.y = ye - ys;
    m.z = xe - xs - 1;
    m.w = 0;
    g_meta[t] = m;
}

__device__ __forceinline__ float4 fmax4(float4 a, float4 b)
{
    return make_float4(fmaxf(a.x, b.x), fmaxf(a.y, b.y),
                       fmaxf(a.z, b.z), fmaxf(a.w, b.w));
}

// ---------------- 3) fused pool + output ----------------
// grid (7, 2, 128): x = i row, y = cg (128 ch), z = roi; 224 thr = 7 warps.
#define SPITCH 132
__global__ __launch_bounds__(224, 8) void roi_pool_kernel(float* __restrict__ out)
{
    __shared__ __align__(16) float s[OUTP * SPITCH];

    int i    = blockIdx.x;
    int cg   = blockIdx.y;
    int n    = blockIdx.z;
    int lane = threadIdx.x & 31;
    int j    = threadIdx.x >> 5;      // 0..6

    int4 m = __ldg(&g_meta[n * NBINS + i * OUTP + j]);
    int wm1 = m.z;

    const float4* base = (const float4*)g_feat_t
                       + (size_t)m.x * CS + cg * 32 + lane;

    float4 acc = make_float4(-FLT_MAX, -FLT_MAX, -FLT_MAX, -FLT_MAX);
    for (int r = 0; r < m.y; ++r) {    // m.y identical across all 7 warps
        const float4* row = base + (size_t)r * (WW * CS);
        float4 v0 = __ldg(row);
        float4 v1 = __ldg(row + min(1, wm1) * CS);
        float4 v2 = __ldg(row + min(2, wm1) * CS);
        float4 v3 = __ldg(row + min(3, wm1) * CS);
        float4 m0 = fmax4(v0, v1);
        float4 m1 = fmax4(v2, v3);
        if (wm1 >= 4) {                // warp-uniform branch
            float4 v4 = __ldg(row + 4 * CS);
            float4 v5 = __ldg(row + min(5, wm1) * CS);
            float4 v6 = __ldg(row + min(6, wm1) * CS);
            float4 v7 = __ldg(row + min(7, wm1) * CS);
            m0 = fmax4(m0, fmax4(v4, v5));
            m1 = fmax4(m1, fmax4(v6, v7));
        }
        acc = fmax4(acc, fmax4(m0, m1));
    }

    *(float4*)&s[j * SPITCH + lane * 4] = acc;
    __syncthreads();

    // out[n][cg*128 + c][i*7 + j]: 128 runs of 7 contiguous floats
    float* dst = out + ((size_t)n * CCH + cg * 128) * NBINS + i * OUTP;
    #pragma unroll
    for (int p = threadIdx.x; p < 128 * OUTP; p += 224) {
        int c  = p / OUTP;
        int jj = p - c * OUTP;
        dst[(size_t)c * NBINS + jj] = s[jj * SPITCH + c];
    }
}

extern "C" void kernel_launch(void* const* d_in, const int* in_sizes, int n_in,
                              void* d_out, int out_size)
{
    const float* feat = (const float*)d_in[0];
    const float* rois = (const float*)d_in[1];
    float* out = (float*)d_out;

    transpose_kernel<<<dim3(79, 2, 2), 256>>>(feat);

    prep_kernel<<<(128 * NBINS + 255) / 256, 256>>>(rois);

    roi_pool_kernel<<<dim3(OUTP, 2, 128), 224>>>(out);
}

// round 12
// speedup vs baseline: 1.1792x; 1.1792x over previous
#include <cuda_runtime.h>
#include <float.h>

// ROI max pool, four-phase, all sync-free except the tiny smem-free kernels:
//  1) transpose: [2,256,50,50] -> g_feat_t [2,50,50,256]; register transpose
//     (coalesced loads, LDG->STG.128, no smem, no barriers, MLP=4)
//  2) prep: per-(roi,bin) bounds -> g_meta
//  3) pool (R9-proven shape): 6272 blocks x 64 thr, warp = bin x 128 ch,
//     width<=8 unrolled clamped loads, float4 coalesced store to g_tmp
//  4) reshape: g_tmp[n][ij][c] -> out[n][c][ij]; register transpose
//     (LDG.128 per lane, coalesced stores, no smem, no barriers)

#define OUTP 7
#define NBINS 49
#define CCH  256
#define HH   50
#define WW   50
#define HWSZ (HH * WW)
#define BB   2
#define CS   (CCH / 4)

__device__ __align__(16) float g_feat_t[BB * HWSZ * CCH];   // 5.12 MB
__device__ __align__(16) float g_tmp[128 * NBINS * CCH];    // 6.42 MB
__device__ int4 g_meta[128 * NBINS];

// ---------------- 1) transpose, register-only ----------------
// grid (79, 8, 2): x = 32-hw chunk, y = 32-ch slab, z = b; 256 thr = 8 warps.
// warp w: channels cbase+4w..+3; lane: hw. 4 coalesced LDG, 1 STG.128.
__global__ __launch_bounds__(256) void transpose_kernel(const float* __restrict__ feat)
{
    int b    = blockIdx.z;
    int hw0  = blockIdx.x * 32;
    int c0   = blockIdx.y * 32 + (threadIdx.x >> 5) * 4;
    int lane = threadIdx.x & 31;
    int hw   = hw0 + lane;
    if (hw < HWSZ) {
        const float* src = feat + ((size_t)b * CCH + c0) * HWSZ + hw;
        float4 o;
        o.x = __ldg(src);
        o.y = __ldg(src + HWSZ);
        o.z = __ldg(src + 2 * HWSZ);
        o.w = __ldg(src + 3 * HWSZ);
        *(float4*)(g_feat_t + ((size_t)b * HWSZ + hw) * CCH + c0) = o;
    }
}

// ---------------- 2) prep ----------------
__global__ void prep_kernel(const float* __restrict__ rois)
{
    int t = blockIdx.x * blockDim.x + threadIdx.x;
    if (t >= 128 * NBINS) return;
    int n  = t / NBINS;
    int ij = t - n * NBINS;
    int i  = ij / OUTP;
    int j  = ij - i * OUTP;

    const float* r = rois + n * 5;
    int im = (int)rintf(r[0]);
    int x1 = (int)rintf(r[1] * 0.0625f);
    int y1 = (int)rintf(r[2] * 0.0625f);
    int x2 = (int)rintf(r[3] * 0.0625f);
    int y2 = (int)rintf(r[4] * 0.0625f);
    unsigned h = (unsigned)(y2 - y1 + 1);
    unsigned w = (unsigned)(x2 - x1 + 1);

    int ys = (int)((unsigned)(i * h) / 7u) + y1;
    int ye = (int)(((unsigned)((i + 1) * h) + 6u) / 7u) + y1;
    int xs = (int)((unsigned)(j * w) / 7u) + x1;
    int xe = (int)(((unsigned)((j + 1) * w) + 6u) / 7u) + x1;
    ye = min(ye, HH);  xe = min(xe, WW);

    int4 m;
    m.x = im * HWSZ + ys * WW + xs;
    m.y = ye - ys;
    m.z = xe - xs - 1;
    m.w = 0;
    g_meta[t] = m;
}

__device__ __forceinline__ float4 fmax4(float4 a, float4 b)
{
    return make_float4(fmaxf(a.x, b.x), fmaxf(a.y, b.y),
                       fmaxf(a.z, b.z), fmaxf(a.w, b.w));
}

// ---------------- 3) pool: 6272 blocks x 64 threads (R9-proven) ------------
__global__ __launch_bounds__(64) void roi_pool_kernel(void)
{
    int task = blockIdx.x;            // n*NBINS + ij
    int lane = threadIdx.x & 31;
    int cg   = threadIdx.x >> 5;

    int4 m = __ldg(&g_meta[task]);
    int wm1 = m.z;

    const float4* base = (const float4*)g_feat_t
                       + (size_t)m.x * CS + cg * 32 + lane;

    float4 acc = make_float4(-FLT_MAX, -FLT_MAX, -FLT_MAX, -FLT_MAX);
    for (int r = 0; r < m.y; ++r) {
        const float4* row = base + (size_t)r * (WW * CS);
        float4 v0 = __ldg(row);
        float4 v1 = __ldg(row + min(1, wm1) * CS);
        float4 v2 = __ldg(row + min(2, wm1) * CS);
        float4 v3 = __ldg(row + min(3, wm1) * CS);
        float4 m0 = fmax4(v0, v1);
        float4 m1 = fmax4(v2, v3);
        if (wm1 >= 4) {               // warp-uniform branch
            float4 v4 = __ldg(row + 4 * CS);
            float4 v5 = __ldg(row + min(5, wm1) * CS);
            float4 v6 = __ldg(row + min(6, wm1) * CS);
            float4 v7 = __ldg(row + min(7, wm1) * CS);
            m0 = fmax4(m0, fmax4(v4, v5));
            m1 = fmax4(m1, fmax4(v6, v7));
        }
        acc = fmax4(acc, fmax4(m0, m1));
    }

    ((float4*)g_tmp)[(size_t)task * (CCH / 4) + cg * 32 + lane] = acc;
}

// ---------------- 4) reshape, register-only ----------------
// grid (16, 128): 8 warps/block; warp-task = (c-quad, ij-half).
// lane: ij; LDG.128 of 4 consecutive channels; 4 coalesced store sweeps.
__global__ __launch_bounds__(256) void reshape_kernel(float* __restrict__ out)
{
    int n    = blockIdx.y;
    int task = blockIdx.x * 8 + (threadIdx.x >> 5);   // 0..127
    int lane = threadIdx.x & 31;
    int cq   = task >> 1;                             // 0..63
    int ij   = (task & 1) * 32 + lane;
    if (ij < NBINS) {
        float4 v = *(const float4*)(g_tmp + ((size_t)n * NBINS + ij) * CCH + cq * 4);
        float* dst = out + ((size_t)n * CCH + cq * 4) * NBINS + ij;
        dst[0 * NBINS] = v.x;
        dst[1 * NBINS] = v.y;
        dst[2 * NBINS] = v.z;
        dst[3 * NBINS] = v.w;
    }
}

extern "C" void kernel_launch(void* const* d_in, const int* in_sizes, int n_in,
                              void* d_out, int out_size)
{
    const float* feat = (const float*)d_in[0];
    const float* rois = (const float*)d_in[1];
    float* out = (float*)d_out;

    transpose_kernel<<<dim3(79, 8, 2), 256>>>(feat);

    prep_kernel<<<(128 * NBINS + 255) / 256, 256>>>(rois);

    roi_pool_kernel<<<128 * NBINS, 64>>>();

    reshape_kernel<<<dim3(16, 128), 256>>>(out);
}